// round 6
// baseline (speedup 1.0000x reference)
#include <cuda_runtime.h>

#define NN   100000
#define EE   3200000
#define GG   64
#define INC  128
#define HIDC 16
#define OUTC 8
#define EDGC 16
#define NBMX 128        // ceil(NN/1024) = 98 scan blocks

// ---------------- scratch ----------------
__device__ int2  g_sd[EE];        // {src,dst} packed
__device__ int   g_rank[EE];      // within-dst rank (from k_deg atomic return)
__device__ int   g_deg[NN];
__device__ float g_dinv[NN];
__device__ int   g_rploc[NN];     // block-local exclusive scan of deg
__device__ int   g_btot[NBMX];
__device__ int   g_boff[NBMX];
__device__ int2  g_cpack[EE];     // {src, norm} grouped by dst
__device__ float g_A[NN * HIDC];
__device__ float g_emb1[NN * HIDC];
__device__ float g_agg1[NN * HIDC];
__device__ float g_emb2[NN * HIDC];
__device__ float g_agg2[NN * HIDC];
__device__ float g_pool[GG * HIDC];
__device__ int   g_cnt[GG];
__device__ int   g_done;          // edge2 last-block counter
__device__ int   g_done2;         // scanA last-block counter
__device__ int   g_w64;

__device__ __forceinline__ void red_add_v4(float* p, float4 v) {
    asm volatile("red.global.add.v4.f32 [%0], {%1,%2,%3,%4};"
                 :: "l"(p), "f"(v.x), "f"(v.y), "f"(v.z), "f"(v.w)
                 : "memory");
}

// ---------------- kernels ----------------

// detect dtype + zero accumulators
__global__ void k_pre(const unsigned* __restrict__ ei, int n_nodes) {
    int t = blockIdx.x * blockDim.x + threadIdx.x;
    if (t == 0) {
        int ok = 1;
#pragma unroll
        for (int k = 0; k < 8; k++)
            if (ei[2 * k + 1] != 0u) ok = 0;
        g_w64 = ok;
        g_done = 0;
        g_done2 = 0;
    }
    if (t < n_nodes) g_deg[t] = 0;
    if (t < n_nodes * HIDC) g_A[t] = 0.f;
    if (t < GG * HIDC) g_pool[t] = 0.f;
    if (t < GG) g_cnt[t] = 0;
}

// edge_index -> packed int2 + rank (atomic return) + degree histogram
__global__ void k_deg(const void* __restrict__ ei, int E) {
    int e = blockIdx.x * blockDim.x + threadIdx.x;
    if (e >= E) return;
    int s, d;
    if (g_w64) {
        const long long* p = (const long long*)ei;
        s = (int)p[e]; d = (int)p[E + e];
    } else {
        const int* p = (const int*)ei;
        s = p[e]; d = p[E + e];
    }
    g_sd[e] = make_int2(s, d);
    g_rank[e] = atomicAdd(&g_deg[d], 1);
}

// block-local exclusive scan of deg (1024/block) + dinv; last block scans btot->boff
__global__ void k_scanA(int n_nodes, int nb) {
    __shared__ int s[1024];
    __shared__ int lastblk;
    int tid = threadIdx.x;
    int n = blockIdx.x * 1024 + tid;
    int d = (n < n_nodes) ? g_deg[n] : 0;
    if (n < n_nodes) g_dinv[n] = rsqrtf((float)(d + 1));  // +1 self-loop
    s[tid] = d;
    __syncthreads();
    for (int off = 1; off < 1024; off <<= 1) {
        int t = (tid >= off) ? s[tid - off] : 0;
        __syncthreads();
        s[tid] += t;
        __syncthreads();
    }
    if (n < n_nodes) g_rploc[n] = s[tid] - d;
    if (tid == 1023) g_btot[blockIdx.x] = s[tid];
    __threadfence();
    __syncthreads();
    if (tid == 0) lastblk = (atomicAdd(&g_done2, 1) == gridDim.x - 1);
    __syncthreads();
    if (lastblk) {
        __threadfence();
        int v = (tid < nb) ? g_btot[tid] : 0;
        s[tid] = v;
        __syncthreads();
        for (int off = 1; off < 128; off <<= 1) {
            int t = (tid >= off) ? s[tid - off] : 0;
            __syncthreads();
            s[tid] += t;
            __syncthreads();
        }
        if (tid < nb) g_boff[tid] = s[tid] - v;
    }
}

// FUSED per-edge pass (4 threads/edge), NO atomics:
//  q0: norm, CSR placement via precomputed rank; all: A[dst] += norm*edge_attr
__global__ void k_fuse(const float4* __restrict__ ea4, int E) {
    int t = blockIdx.x * blockDim.x + threadIdx.x;
    if (t >= 4 * E) return;
    unsigned m = __activemask();
    int e = t >> 2, q = t & 3;
    int lane = threadIdx.x & 31;
    float nm = 0.f;
    int d = 0;
    if (q == 0) {
        int2 sd = g_sd[e];
        nm = g_dinv[sd.x] * g_dinv[sd.y];
        d = sd.y;
        int r = g_rploc[d] + g_boff[d >> 10] + g_rank[e];
        g_cpack[r] = make_int2(sd.x, __float_as_int(nm));
    }
    nm = __shfl_sync(m, nm, lane & ~3);
    d  = __shfl_sync(m, d,  lane & ~3);
    float4 v = ea4[t];
    v.x *= nm; v.y *= nm; v.z *= nm; v.w *= nm;
    red_add_v4(&g_A[d * HIDC + q * 4], v);
}

// Layer-1 node transform: emb1 = x @ W1n ; agg1 init = A @ W1e + dinv^2 * emb1
__global__ void k_emb1(const float* __restrict__ x,
                       const float* __restrict__ Wn,
                       const float* __restrict__ We,
                       int n_nodes) {
    __shared__ float sWn[INC * HIDC];
    __shared__ float sWe[HIDC * HIDC];
    int tid = threadIdx.x;
    for (int i = tid; i < INC * HIDC; i += blockDim.x) sWn[i] = Wn[i];
    if (tid < HIDC * HIDC) sWe[tid] = We[tid];
    __syncthreads();
    int t = blockIdx.x * blockDim.x + tid;
    if (t >= n_nodes * HIDC) return;
    int n = t >> 4, c = t & 15;
    const float4* x4 = (const float4*)(x + (size_t)n * INC);
    float acc = 0.f;
#pragma unroll
    for (int j = 0; j < INC / 4; j++) {
        float4 v = x4[j];
        acc = fmaf(v.x, sWn[(4 * j + 0) * HIDC + c], acc);
        acc = fmaf(v.y, sWn[(4 * j + 1) * HIDC + c], acc);
        acc = fmaf(v.z, sWn[(4 * j + 2) * HIDC + c], acc);
        acc = fmaf(v.w, sWn[(4 * j + 3) * HIDC + c], acc);
    }
    const float4* a4 = (const float4*)(g_A + n * HIDC);
    float ae = 0.f;
#pragma unroll
    for (int j = 0; j < HIDC / 4; j++) {
        float4 v = a4[j];
        ae = fmaf(v.x, sWe[(4 * j + 0) * HIDC + c], ae);
        ae = fmaf(v.y, sWe[(4 * j + 1) * HIDC + c], ae);
        ae = fmaf(v.z, sWe[(4 * j + 2) * HIDC + c], ae);
        ae = fmaf(v.w, sWe[(4 * j + 3) * HIDC + c], ae);
    }
    float di = g_dinv[n];
    g_emb1[t] = acc;
    g_agg1[t] = ae + di * di * acc;
}

// FUSED edge pass 1 + layer-2 node transform (warp per node):
//  h = agg1init + gather(norm*emb1[src]);  emb2 = relu(h)@W2n;
//  agg2 init = A@W2e + dinv^2*emb2
__global__ void k_edge1(const float* __restrict__ Wn,
                        const float* __restrict__ We,
                        int n_nodes) {
    __shared__ float sWn[HIDC * HIDC];
    __shared__ float sWe[HIDC * HIDC];
    int tid = threadIdx.x;
    sWn[tid] = Wn[tid];           // blockDim == 256 == HIDC*HIDC
    sWe[tid] = We[tid];
    __syncthreads();
    int w = (blockIdx.x * blockDim.x + tid) >> 5;
    if (w >= n_nodes) return;
    const unsigned F = 0xffffffffu;
    int lane = tid & 31, q = lane & 3, i0 = lane >> 2;
    int beg = g_rploc[w] + g_boff[w >> 10];
    int end = beg + g_deg[w];
    float ax = 0.f, ay = 0.f, az = 0.f, aw = 0.f;
    for (int i = beg + i0; i < end; i += 8) {
        int2 pk = g_cpack[i];
        float nm = __int_as_float(pk.y);
        float4 v = ((const float4*)g_emb1)[(size_t)pk.x * 4 + q];
        ax = fmaf(nm, v.x, ax); ay = fmaf(nm, v.y, ay);
        az = fmaf(nm, v.z, az); aw = fmaf(nm, v.w, aw);
    }
#pragma unroll
    for (int off = 16; off >= 4; off >>= 1) {
        ax += __shfl_down_sync(F, ax, off);
        ay += __shfl_down_sync(F, ay, off);
        az += __shfl_down_sync(F, az, off);
        aw += __shfl_down_sync(F, aw, off);
    }
    if (lane < 4) {
        float4 init = ((const float4*)g_agg1)[w * 4 + lane];
        ax += init.x; ay += init.y; az += init.z; aw += init.w;
    }
    float h[HIDC];
#pragma unroll
    for (int j = 0; j < 4; j++) {
        h[4 * j + 0] = __shfl_sync(F, ax, j);
        h[4 * j + 1] = __shfl_sync(F, ay, j);
        h[4 * j + 2] = __shfl_sync(F, az, j);
        h[4 * j + 3] = __shfl_sync(F, aw, j);
    }
    if (lane < HIDC) {
        const float* Arow = g_A + (size_t)w * HIDC;
        float di = g_dinv[w];
        float acc = 0.f, ae = 0.f;
#pragma unroll
        for (int k = 0; k < HIDC; k++) {
            acc = fmaf(fmaxf(h[k], 0.f), sWn[k * HIDC + lane], acc);
            ae  = fmaf(Arow[k],          sWe[k * HIDC + lane], ae);
        }
        g_emb2[w * HIDC + lane] = acc;
        g_agg2[w * HIDC + lane] = ae + di * di * acc;
    }
}

// FUSED edge pass 2 + pool + final linear (warp per node):
//  agg2 final = agg2init + gather;  pool[batch[n]] += relu(agg2);  last block: out
__global__ void k_edge2(const void* __restrict__ batch,
                        const float* __restrict__ W,
                        const float* __restrict__ b,
                        float* __restrict__ out,
                        int n_nodes, int nblocks) {
    int tid = threadIdx.x;
    int w = (blockIdx.x * blockDim.x + tid) >> 5;
    const unsigned F = 0xffffffffu;
    int lane = tid & 31, q = lane & 3, i0 = lane >> 2;
    if (w < n_nodes) {
        int beg = g_rploc[w] + g_boff[w >> 10];
        int end = beg + g_deg[w];
        float ax = 0.f, ay = 0.f, az = 0.f, aw = 0.f;
        for (int i = beg + i0; i < end; i += 8) {
            int2 pk = g_cpack[i];
            float nm = __int_as_float(pk.y);
            float4 v = ((const float4*)g_emb2)[(size_t)pk.x * 4 + q];
            ax = fmaf(nm, v.x, ax); ay = fmaf(nm, v.y, ay);
            az = fmaf(nm, v.z, az); aw = fmaf(nm, v.w, aw);
        }
#pragma unroll
        for (int off = 16; off >= 4; off >>= 1) {
            ax += __shfl_down_sync(F, ax, off);
            ay += __shfl_down_sync(F, ay, off);
            az += __shfl_down_sync(F, az, off);
            aw += __shfl_down_sync(F, aw, off);
        }
        int g = 0;
        if (lane == 0)
            g = g_w64 ? (int)((const long long*)batch)[w]
                      : ((const int*)batch)[w];
        g = __shfl_sync(F, g, 0);
        if (lane < 4) {
            float4 init = ((const float4*)g_agg2)[w * 4 + lane];
            float4 r = make_float4(fmaxf(init.x + ax, 0.f),
                                   fmaxf(init.y + ay, 0.f),
                                   fmaxf(init.z + az, 0.f),
                                   fmaxf(init.w + aw, 0.f));
            red_add_v4(&g_pool[g * HIDC + lane * 4], r);
        }
        if (lane == 0) atomicAdd(&g_cnt[g], 1);
    }
    // last block computes the final linear
    __shared__ int lastblk;
    __threadfence();
    __syncthreads();
    if (tid == 0) lastblk = (atomicAdd(&g_done, 1) == nblocks - 1);
    __syncthreads();
    if (lastblk) {
        __threadfence();
        for (int t = tid; t < GG * OUTC; t += blockDim.x) {
            int gg = t / OUTC, o = t % OUTC;
            float inv = 1.f / fmaxf((float)g_cnt[gg], 1.f);
            float s = b[o];
#pragma unroll
            for (int k = 0; k < HIDC; k++)
                s = fmaf(g_pool[gg * HIDC + k] * inv, W[k * OUTC + o], s);
            out[t] = s;
        }
    }
}

// ---------------- launch ----------------
extern "C" void kernel_launch(void* const* d_in, const int* in_sizes, int n_in,
                              void* d_out, int out_size) {
    const float* x    = (const float*)d_in[0];
    const void*  ei   = d_in[1];
    const float* ea   = (const float*)d_in[2];
    const void*  bidx = d_in[3];
    const float* W1n  = (const float*)d_in[4];
    const float* W1e  = (const float*)d_in[5];
    const float* W2n  = (const float*)d_in[6];
    const float* W2e  = (const float*)d_in[7];
    const float* nW   = (const float*)d_in[8];
    const float* nb   = (const float*)d_in[9];
    float* out = (float*)d_out;

    int N = in_sizes[0] / INC;
    int E = in_sizes[2] / EDGC;
    if (N > NN) N = NN;
    if (E > EE) E = EE;
    int nb_scan = (N + 1023) / 1024;

    const int B = 256;
    int gridW = (N + (B / 32) - 1) / (B / 32);

    k_pre  <<<(N * HIDC + B - 1) / B, B>>>((const unsigned*)ei, N);   // 0
    k_deg  <<<(E + B - 1) / B, B>>>(ei, E);                           // 1
    k_scanA<<<nb_scan, 1024>>>(N, nb_scan);                           // 2
    k_fuse <<<(4 * E + B - 1) / B, B>>>((const float4*)ea, E);        // 3 <- profiled
    k_emb1 <<<(N * HIDC + B - 1) / B, B>>>(x, W1n, W1e, N);           // 4
    k_edge1<<<gridW, B>>>(W2n, W2e, N);                               // 5
    k_edge2<<<gridW, B>>>(bidx, nW, nb, out, N, gridW);               // 6
}

// round 7
// speedup vs baseline: 1.1158x; 1.1158x over previous
#include <cuda_runtime.h>

#define NN   100000
#define EE   3200000
#define GG   64
#define INC  128
#define HIDC 16
#define OUTC 8
#define EDGC 16
#define NBMX 128        // ceil(NN/1024) = 98 scan blocks

// ---------------- scratch ----------------
__device__ int2  g_sd[EE];        // {src,dst} packed
__device__ int   g_rank[EE];      // within-dst rank (from k_deg atomic return)
__device__ int   g_deg[NN];
__device__ float g_dinv[NN];
__device__ int   g_rploc[NN];     // block-local exclusive scan of deg
__device__ int   g_btot[NBMX];
__device__ int   g_boff[NBMX];
__device__ int2  g_cpack[EE];     // {src, norm} grouped by dst
__device__ float g_A[NN * HIDC];
__device__ float g_emb1[NN * HIDC];
__device__ float g_emb2[NN * HIDC];
__device__ float g_agg2[NN * HIDC];
__device__ float g_pool[GG * HIDC];
__device__ int   g_cnt[GG];
__device__ int   g_done;          // pool last-block counter
__device__ int   g_done2;         // scanA last-block counter
__device__ int   g_w64;

__device__ __forceinline__ void red_add_v4(float* p, float4 v) {
    asm volatile("red.global.add.v4.f32 [%0], {%1,%2,%3,%4};"
                 :: "l"(p), "f"(v.x), "f"(v.y), "f"(v.z), "f"(v.w)
                 : "memory");
}

// ---------------- kernels ----------------

// detect dtype + zero accumulators
__global__ void k_pre(const unsigned* __restrict__ ei, int n_nodes) {
    int t = blockIdx.x * blockDim.x + threadIdx.x;
    if (t == 0) {
        int ok = 1;
#pragma unroll
        for (int k = 0; k < 8; k++)
            if (ei[2 * k + 1] != 0u) ok = 0;
        g_w64 = ok;
        g_done = 0;
        g_done2 = 0;
    }
    if (t < n_nodes) g_deg[t] = 0;
    if (t < n_nodes * HIDC) g_A[t] = 0.f;
    if (t < GG * HIDC) g_pool[t] = 0.f;
    if (t < GG) g_cnt[t] = 0;
}

// edge_index -> packed int2 + rank (atomic return) + degree histogram
__global__ void k_deg(const void* __restrict__ ei, int E) {
    int e = blockIdx.x * blockDim.x + threadIdx.x;
    if (e >= E) return;
    int s, d;
    if (g_w64) {
        const long long* p = (const long long*)ei;
        s = (int)p[e]; d = (int)p[E + e];
    } else {
        const int* p = (const int*)ei;
        s = p[e]; d = p[E + e];
    }
    g_sd[e] = make_int2(s, d);
    g_rank[e] = atomicAdd(&g_deg[d], 1);
}

// block-local exclusive scan of deg (1024/block) + dinv; last block scans btot->boff
__global__ void k_scanA(int n_nodes, int nb) {
    __shared__ int s[1024];
    __shared__ int lastblk;
    int tid = threadIdx.x;
    int n = blockIdx.x * 1024 + tid;
    int d = (n < n_nodes) ? g_deg[n] : 0;
    if (n < n_nodes) g_dinv[n] = rsqrtf((float)(d + 1));  // +1 self-loop
    s[tid] = d;
    __syncthreads();
    for (int off = 1; off < 1024; off <<= 1) {
        int t = (tid >= off) ? s[tid - off] : 0;
        __syncthreads();
        s[tid] += t;
        __syncthreads();
    }
    if (n < n_nodes) g_rploc[n] = s[tid] - d;
    if (tid == 1023) g_btot[blockIdx.x] = s[tid];
    __threadfence();
    __syncthreads();
    if (tid == 0) lastblk = (atomicAdd(&g_done2, 1) == gridDim.x - 1);
    __syncthreads();
    if (lastblk) {
        __threadfence();
        int v = (tid < nb) ? g_btot[tid] : 0;
        s[tid] = v;
        __syncthreads();
        for (int off = 1; off < 128; off <<= 1) {
            int t = (tid >= off) ? s[tid - off] : 0;
            __syncthreads();
            s[tid] += t;
            __syncthreads();
        }
        if (tid < nb) g_boff[tid] = s[tid] - v;
    }
}

// FUSED per-edge pass (4 threads/edge), NO atomics-with-return:
//  q0: norm, CSR placement via precomputed rank; all: A[dst] += norm*edge_attr
__global__ void k_fuse(const float4* __restrict__ ea4, int E) {
    int t = blockIdx.x * blockDim.x + threadIdx.x;
    if (t >= 4 * E) return;
    float4 v = __ldcs(&ea4[t]);       // stream-once: issue first, bypass L2 persist
    unsigned m = __activemask();
    int e = t >> 2, q = t & 3;
    int lane = threadIdx.x & 31;
    float nm = 0.f;
    int d = 0;
    if (q == 0) {
        int2 sd = g_sd[e];
        nm = g_dinv[sd.x] * g_dinv[sd.y];
        d = sd.y;
        int r = g_rploc[d] + g_boff[d >> 10] + g_rank[e];
        g_cpack[r] = make_int2(sd.x, __float_as_int(nm));
    }
    nm = __shfl_sync(m, nm, lane & ~3);
    d  = __shfl_sync(m, d,  lane & ~3);
    v.x *= nm; v.y *= nm; v.z *= nm; v.w *= nm;
    red_add_v4(&g_A[d * HIDC + q * 4], v);
}

// Pure layer-1 node transform: emb1 = x @ W1n
__global__ void k_emb1(const float* __restrict__ x,
                       const float* __restrict__ Wn,
                       int n_nodes) {
    __shared__ float sWn[INC * HIDC];
    int tid = threadIdx.x;
    for (int i = tid; i < INC * HIDC; i += blockDim.x) sWn[i] = Wn[i];
    __syncthreads();
    int t = blockIdx.x * blockDim.x + tid;
    if (t >= n_nodes * HIDC) return;
    int n = t >> 4, c = t & 15;
    const float4* x4 = (const float4*)(x + (size_t)n * INC);
    float acc = 0.f;
#pragma unroll
    for (int j = 0; j < INC / 4; j++) {
        float4 v = __ldcs(&x4[j]);
        acc = fmaf(v.x, sWn[(4 * j + 0) * HIDC + c], acc);
        acc = fmaf(v.y, sWn[(4 * j + 1) * HIDC + c], acc);
        acc = fmaf(v.z, sWn[(4 * j + 2) * HIDC + c], acc);
        acc = fmaf(v.w, sWn[(4 * j + 3) * HIDC + c], acc);
    }
    g_emb1[t] = acc;
}

// FUSED edge pass 1 + layer-2 node transform (warp per node):
//  h = (A@W1e + dinv^2*emb1[w]) + gather(norm*emb1[src]);  emb2 = relu(h)@W2n
__global__ void k_edge1(const float* __restrict__ We1,
                        const float* __restrict__ Wn2,
                        int n_nodes) {
    __shared__ float sWe1[HIDC * HIDC];
    __shared__ float sWn2[HIDC * HIDC];
    int tid = threadIdx.x;
    sWe1[tid] = We1[tid];         // blockDim == 256 == HIDC*HIDC
    sWn2[tid] = Wn2[tid];
    __syncthreads();
    int w = (blockIdx.x * blockDim.x + tid) >> 5;
    if (w >= n_nodes) return;
    const unsigned F = 0xffffffffu;
    int lane = tid & 31, q = lane & 3, i0 = lane >> 2;
    int beg = g_rploc[w] + g_boff[w >> 10];
    int end = beg + g_deg[w];
    float ax = 0.f, ay = 0.f, az = 0.f, aw = 0.f;
    for (int i = beg + i0; i < end; i += 8) {
        int2 pk = g_cpack[i];
        float nm = __int_as_float(pk.y);
        float4 v = ((const float4*)g_emb1)[(size_t)pk.x * 4 + q];
        ax = fmaf(nm, v.x, ax); ay = fmaf(nm, v.y, ay);
        az = fmaf(nm, v.z, az); aw = fmaf(nm, v.w, aw);
    }
#pragma unroll
    for (int off = 16; off >= 4; off >>= 1) {
        ax += __shfl_down_sync(F, ax, off);
        ay += __shfl_down_sync(F, ay, off);
        az += __shfl_down_sync(F, az, off);
        aw += __shfl_down_sync(F, aw, off);
    }
    if (lane < 4) {                // q == lane, i0 == 0: holds quad q totals
        float di = g_dinv[w], di2 = di * di;
        const float* Arow = g_A + (size_t)w * HIDC;
        float4 e1 = ((const float4*)g_emb1)[w * 4 + lane];
        float ix = di2 * e1.x, iy = di2 * e1.y, iz = di2 * e1.z, iw = di2 * e1.w;
#pragma unroll
        for (int k = 0; k < HIDC; k++) {
            float a = Arow[k];
            ix = fmaf(a, sWe1[k * HIDC + lane * 4 + 0], ix);
            iy = fmaf(a, sWe1[k * HIDC + lane * 4 + 1], iy);
            iz = fmaf(a, sWe1[k * HIDC + lane * 4 + 2], iz);
            iw = fmaf(a, sWe1[k * HIDC + lane * 4 + 3], iw);
        }
        ax += ix; ay += iy; az += iz; aw += iw;
    }
    float h[HIDC];
#pragma unroll
    for (int j = 0; j < 4; j++) {
        h[4 * j + 0] = __shfl_sync(F, ax, j);
        h[4 * j + 1] = __shfl_sync(F, ay, j);
        h[4 * j + 2] = __shfl_sync(F, az, j);
        h[4 * j + 3] = __shfl_sync(F, aw, j);
    }
    if (lane < HIDC) {
        float acc = 0.f;
#pragma unroll
        for (int k = 0; k < HIDC; k++)
            acc = fmaf(fmaxf(h[k], 0.f), sWn2[k * HIDC + lane], acc);
        g_emb2[w * HIDC + lane] = acc;
    }
}

// FUSED edge pass 2 (warp per node):
//  agg2 = (A@W2e + dinv^2*emb2[w]) + gather(norm*emb2[src])
__global__ void k_edge2(const float* __restrict__ We2, int n_nodes) {
    __shared__ float sWe2[HIDC * HIDC];
    int tid = threadIdx.x;
    sWe2[tid] = We2[tid];
    __syncthreads();
    int w = (blockIdx.x * blockDim.x + tid) >> 5;
    if (w >= n_nodes) return;
    const unsigned F = 0xffffffffu;
    int lane = tid & 31, q = lane & 3, i0 = lane >> 2;
    int beg = g_rploc[w] + g_boff[w >> 10];
    int end = beg + g_deg[w];
    float ax = 0.f, ay = 0.f, az = 0.f, aw = 0.f;
    for (int i = beg + i0; i < end; i += 8) {
        int2 pk = g_cpack[i];
        float nm = __int_as_float(pk.y);
        float4 v = ((const float4*)g_emb2)[(size_t)pk.x * 4 + q];
        ax = fmaf(nm, v.x, ax); ay = fmaf(nm, v.y, ay);
        az = fmaf(nm, v.z, az); aw = fmaf(nm, v.w, aw);
    }
#pragma unroll
    for (int off = 16; off >= 4; off >>= 1) {
        ax += __shfl_down_sync(F, ax, off);
        ay += __shfl_down_sync(F, ay, off);
        az += __shfl_down_sync(F, az, off);
        aw += __shfl_down_sync(F, aw, off);
    }
    if (lane < 4) {
        float di = g_dinv[w], di2 = di * di;
        const float* Arow = g_A + (size_t)w * HIDC;
        float4 e2 = ((const float4*)g_emb2)[w * 4 + lane];
        float ix = di2 * e2.x, iy = di2 * e2.y, iz = di2 * e2.z, iw = di2 * e2.w;
#pragma unroll
        for (int k = 0; k < HIDC; k++) {
            float a = Arow[k];
            ix = fmaf(a, sWe2[k * HIDC + lane * 4 + 0], ix);
            iy = fmaf(a, sWe2[k * HIDC + lane * 4 + 1], iy);
            iz = fmaf(a, sWe2[k * HIDC + lane * 4 + 2], iz);
            iw = fmaf(a, sWe2[k * HIDC + lane * 4 + 3], iw);
        }
        ((float4*)g_agg2)[w * 4 + lane] =
            make_float4(ax + ix, ay + iy, az + iz, aw + iw);
    }
}

// pool (warp-uniform shfl reduce over 32 sorted nodes) + fused final linear
__global__ void k_pool(const void* __restrict__ batch,
                       const float* __restrict__ W,
                       const float* __restrict__ b,
                       float* __restrict__ out,
                       int n_nodes, int nblocks) {
    int tid = threadIdx.x;
    int n = blockIdx.x * blockDim.x + tid;
    int g = -1;
    if (n < n_nodes)
        g = g_w64 ? (int)((const long long*)batch)[n] : ((const int*)batch)[n];
    const unsigned full = 0xffffffffu;
    int g0 = __shfl_sync(full, g, 0);
    bool uni = __all_sync(full, g == g0);
    if (uni && g0 >= 0) {
        float ch[HIDC];
#pragma unroll
        for (int c = 0; c < HIDC; c++) {
            float v = fmaxf(g_agg2[n * HIDC + c], 0.f);
#pragma unroll
            for (int off = 16; off >= 1; off >>= 1)
                v += __shfl_down_sync(full, v, off);
            ch[c] = v;
        }
        if ((tid & 31) == 0) {
            red_add_v4(&g_pool[g0 * HIDC + 0],  make_float4(ch[0],  ch[1],  ch[2],  ch[3]));
            red_add_v4(&g_pool[g0 * HIDC + 4],  make_float4(ch[4],  ch[5],  ch[6],  ch[7]));
            red_add_v4(&g_pool[g0 * HIDC + 8],  make_float4(ch[8],  ch[9],  ch[10], ch[11]));
            red_add_v4(&g_pool[g0 * HIDC + 12], make_float4(ch[12], ch[13], ch[14], ch[15]));
            atomicAdd(&g_cnt[g0], 32);
        }
    } else if (n < n_nodes) {
        atomicAdd(&g_cnt[g], 1);
#pragma unroll
        for (int c = 0; c < HIDC; c++)
            atomicAdd(&g_pool[g * HIDC + c], fmaxf(g_agg2[n * HIDC + c], 0.f));
    }
    // last block computes the final linear
    __shared__ int lastblk;
    __threadfence();
    __syncthreads();
    if (tid == 0) lastblk = (atomicAdd(&g_done, 1) == nblocks - 1);
    __syncthreads();
    if (lastblk) {
        __threadfence();
        for (int t = tid; t < GG * OUTC; t += blockDim.x) {
            int gg = t / OUTC, o = t % OUTC;
            float inv = 1.f / fmaxf((float)g_cnt[gg], 1.f);
            float s = b[o];
#pragma unroll
            for (int k = 0; k < HIDC; k++)
                s = fmaf(g_pool[gg * HIDC + k] * inv, W[k * OUTC + o], s);
            out[t] = s;
        }
    }
}

// ---------------- launch ----------------
extern "C" void kernel_launch(void* const* d_in, const int* in_sizes, int n_in,
                              void* d_out, int out_size) {
    const float* x    = (const float*)d_in[0];
    const void*  ei   = d_in[1];
    const float* ea   = (const float*)d_in[2];
    const void*  bidx = d_in[3];
    const float* W1n  = (const float*)d_in[4];
    const float* W1e  = (const float*)d_in[5];
    const float* W2n  = (const float*)d_in[6];
    const float* W2e  = (const float*)d_in[7];
    const float* nW   = (const float*)d_in[8];
    const float* nb   = (const float*)d_in[9];
    float* out = (float*)d_out;

    int N = in_sizes[0] / INC;
    int E = in_sizes[2] / EDGC;
    if (N > NN) N = NN;
    if (E > EE) E = EE;
    int nb_scan = (N + 1023) / 1024;

    const int B = 256;
    int gridW = (N + (B / 32) - 1) / (B / 32);
    int gridP = (N + B - 1) / B;

    k_pre  <<<(N * HIDC + B - 1) / B, B>>>((const unsigned*)ei, N);   // 0
    k_deg  <<<(E + B - 1) / B, B>>>(ei, E);                           // 1
    k_scanA<<<nb_scan, 1024>>>(N, nb_scan);                           // 2
    k_fuse <<<(4 * E + B - 1) / B, B>>>((const float4*)ea, E);        // 3 <- profiled
    k_emb1 <<<(N * HIDC + B - 1) / B, B>>>(x, W1n, N);                // 4
    k_edge1<<<gridW, B>>>(W1e, W2n, N);                               // 5
    k_edge2<<<gridW, B>>>(W2e, N);                                    // 6
    k_pool <<<gridP, B>>>(bidx, nW, nb, out, N, gridP);               // 7
}

// round 8
// speedup vs baseline: 1.2411x; 1.1122x over previous
#include <cuda_runtime.h>

#define NN   100000
#define EE   3200000
#define GG   64
#define INC  128
#define HIDC 16
#define OUTC 8
#define EDGC 16
#define NBMX 128        // ceil(NN/1024) = 98 scan blocks

// ---------------- scratch ----------------
__device__ int2  g_sd[EE];        // {src,dst} packed
__device__ int   g_rank[EE];      // within-dst rank (from k_deg atomic return)
__device__ int   g_deg[NN];
__device__ float g_dinv[NN];
__device__ int   g_rploc[NN];     // block-local exclusive scan of deg
__device__ int   g_btot[NBMX];
__device__ int   g_boff[NBMX];
__device__ int2  g_cpack[EE];     // {src, norm} grouped by dst
__device__ float g_A[NN * HIDC];
__device__ float g_emb1[NN * HIDC];
__device__ float g_agg1[NN * HIDC];
__device__ float g_emb2[NN * HIDC];
__device__ float g_agg2[NN * HIDC];
__device__ float g_pool[GG * HIDC];
__device__ int   g_cnt[GG];
__device__ int   g_done;          // pool last-block counter
__device__ int   g_done2;         // scanA last-block counter
__device__ int   g_w64;

__device__ __forceinline__ void red_add_v4(float* p, float4 v) {
    asm volatile("red.global.add.v4.f32 [%0], {%1,%2,%3,%4};"
                 :: "l"(p), "f"(v.x), "f"(v.y), "f"(v.z), "f"(v.w)
                 : "memory");
}

// ---------------- kernels ----------------

// detect dtype + zero small accumulators (N threads)
__global__ void k_pre(const unsigned* __restrict__ ei, int n_nodes) {
    int t = blockIdx.x * blockDim.x + threadIdx.x;
    if (t == 0) {
        int ok = 1;
#pragma unroll
        for (int k = 0; k < 8; k++)
            if (ei[2 * k + 1] != 0u) ok = 0;
        g_w64 = ok;
        g_done = 0;
        g_done2 = 0;
    }
    if (t < n_nodes) g_deg[t] = 0;
    if (t < GG * HIDC) g_pool[t] = 0.f;
    if (t < GG) g_cnt[t] = 0;
}

// edge_index -> packed int2 + rank (atomic return) + degree histogram
__global__ void k_deg(const void* __restrict__ ei, int E) {
    int e = blockIdx.x * blockDim.x + threadIdx.x;
    if (e >= E) return;
    int s, d;
    if (g_w64) {
        const longlong2* p0 = (const longlong2*)ei;   // 2 edges per 16B — still per-elem ok
        s = (int)__ldcs((const long long*)ei + e);
        d = (int)__ldcs((const long long*)ei + E + e);
        (void)p0;
    } else {
        s = __ldcs((const int*)ei + e);
        d = __ldcs((const int*)ei + E + e);
    }
    g_sd[e] = make_int2(s, d);
    g_rank[e] = atomicAdd(&g_deg[d], 1);
}

// block-local exclusive scan of deg (1024/block) + dinv + zero g_A slice;
// last finishing block scans btot->boff
__global__ void k_scanA(int n_nodes, int nb) {
    __shared__ int s[1024];
    __shared__ int lastblk;
    int tid = threadIdx.x;
    int n = blockIdx.x * 1024 + tid;
    int d = (n < n_nodes) ? g_deg[n] : 0;
    if (n < n_nodes) g_dinv[n] = rsqrtf((float)(d + 1));  // +1 self-loop
    // zero this block's slice of g_A (coalesced)
    {
        size_t base = (size_t)blockIdx.x * 1024 * HIDC;
        size_t lim = (size_t)n_nodes * HIDC;
        for (int i = tid; i < 1024 * HIDC; i += 1024) {
            size_t idx = base + i;
            if (idx < lim) g_A[idx] = 0.f;
        }
    }
    s[tid] = d;
    __syncthreads();
    for (int off = 1; off < 1024; off <<= 1) {
        int t = (tid >= off) ? s[tid - off] : 0;
        __syncthreads();
        s[tid] += t;
        __syncthreads();
    }
    if (n < n_nodes) g_rploc[n] = s[tid] - d;
    if (tid == 1023) g_btot[blockIdx.x] = s[tid];
    __threadfence();
    __syncthreads();
    if (tid == 0) lastblk = (atomicAdd(&g_done2, 1) == gridDim.x - 1);
    __syncthreads();
    if (lastblk) {
        __threadfence();
        int v = (tid < nb) ? g_btot[tid] : 0;
        s[tid] = v;
        __syncthreads();
        for (int off = 1; off < 128; off <<= 1) {
            int t = (tid >= off) ? s[tid - off] : 0;
            __syncthreads();
            s[tid] += t;
            __syncthreads();
        }
        if (tid < nb) g_boff[tid] = s[tid] - v;
    }
}

// FUSED per-edge pass (4 threads/edge), no atomics-with-return:
//  q0: norm + CSR placement via precomputed rank; all: A[dst] += norm*edge_attr
__global__ void k_fuse(const float4* __restrict__ ea4, int E) {
    int t = blockIdx.x * blockDim.x + threadIdx.x;
    if (t >= 4 * E) return;
    float4 v = __ldcs(&ea4[t]);       // stream-once
    unsigned m = __activemask();
    int e = t >> 2, q = t & 3;
    int lane = threadIdx.x & 31;
    float nm = 0.f;
    int d = 0;
    if (q == 0) {
        int2 sd = __ldcs(&g_sd[e]);
        nm = g_dinv[sd.x] * g_dinv[sd.y];
        d = sd.y;
        int r = g_rploc[d] + g_boff[d >> 10] + __ldcs(&g_rank[e]);
        g_cpack[r] = make_int2(sd.x, __float_as_int(nm));
    }
    nm = __shfl_sync(m, nm, lane & ~3);
    d  = __shfl_sync(m, d,  lane & ~3);
    v.x *= nm; v.y *= nm; v.z *= nm; v.w *= nm;
    red_add_v4(&g_A[d * HIDC + q * 4], v);
}

// Layer-1: emb1 = x @ W1n ; agg1 init = A @ W1e + dinv^2 * emb1
__global__ void k_emb1(const float* __restrict__ x,
                       const float* __restrict__ Wn,
                       const float* __restrict__ We,
                       int n_nodes) {
    __shared__ float sWn[INC * HIDC];
    __shared__ float sWe[HIDC * HIDC];
    int tid = threadIdx.x;
    for (int i = tid; i < INC * HIDC; i += blockDim.x) sWn[i] = Wn[i];
    if (tid < HIDC * HIDC) sWe[tid] = We[tid];
    __syncthreads();
    int t = blockIdx.x * blockDim.x + tid;
    if (t >= n_nodes * HIDC) return;
    int n = t >> 4, c = t & 15;
    const float4* x4 = (const float4*)(x + (size_t)n * INC);
    float acc = 0.f;
#pragma unroll
    for (int j = 0; j < INC / 4; j++) {
        float4 v = __ldcs(&x4[j]);
        acc = fmaf(v.x, sWn[(4 * j + 0) * HIDC + c], acc);
        acc = fmaf(v.y, sWn[(4 * j + 1) * HIDC + c], acc);
        acc = fmaf(v.z, sWn[(4 * j + 2) * HIDC + c], acc);
        acc = fmaf(v.w, sWn[(4 * j + 3) * HIDC + c], acc);
    }
    const float4* a4 = (const float4*)(g_A + n * HIDC);
    float ae = 0.f;
#pragma unroll
    for (int j = 0; j < HIDC / 4; j++) {
        float4 v = a4[j];
        ae = fmaf(v.x, sWe[(4 * j + 0) * HIDC + c], ae);
        ae = fmaf(v.y, sWe[(4 * j + 1) * HIDC + c], ae);
        ae = fmaf(v.z, sWe[(4 * j + 2) * HIDC + c], ae);
        ae = fmaf(v.w, sWe[(4 * j + 3) * HIDC + c], ae);
    }
    float di = g_dinv[n];
    g_emb1[t] = acc;
    g_agg1[t] = ae + di * di * acc;
}

// CSR edge pass: warp per node, agg[n] += sum norm_e * emb[src_e]  (no atomics)
__global__ void k_edge(int layer, int n_nodes) {
    const float4* emb = (const float4*)(layer == 1 ? g_emb1 : g_emb2);
    float4* agg = (float4*)(layer == 1 ? g_agg1 : g_agg2);
    int w = (blockIdx.x * blockDim.x + threadIdx.x) >> 5;
    if (w >= n_nodes) return;
    int lane = threadIdx.x & 31, q = lane & 3, i0 = lane >> 2;
    int beg = g_rploc[w] + g_boff[w >> 10];
    int end = beg + g_deg[w];
    float ax = 0.f, ay = 0.f, az = 0.f, aw = 0.f;
    for (int i = beg + i0; i < end; i += 8) {
        int2 pk = g_cpack[i];
        float nm = __int_as_float(pk.y);
        float4 v = __ldg(&emb[(size_t)pk.x * 4 + q]);
        ax = fmaf(nm, v.x, ax); ay = fmaf(nm, v.y, ay);
        az = fmaf(nm, v.z, az); aw = fmaf(nm, v.w, aw);
    }
#pragma unroll
    for (int off = 16; off >= 4; off >>= 1) {
        ax += __shfl_down_sync(0xffffffffu, ax, off);
        ay += __shfl_down_sync(0xffffffffu, ay, off);
        az += __shfl_down_sync(0xffffffffu, az, off);
        aw += __shfl_down_sync(0xffffffffu, aw, off);
    }
    if (lane < 4) {
        float4 o = agg[w * 4 + lane];
        o.x += ax; o.y += ay; o.z += az; o.w += aw;
        agg[w * 4 + lane] = o;
    }
}

// Layer-2: emb2 = relu(agg1) @ W2n ; agg2 init = A @ W2e + dinv^2 * emb2
__global__ void k_emb2(const float* __restrict__ Wn,
                       const float* __restrict__ We,
                       int n_nodes) {
    __shared__ float sWn[HIDC * HIDC];
    __shared__ float sWe[HIDC * HIDC];
    int tid = threadIdx.x;
    if (tid < HIDC * HIDC) { sWn[tid] = Wn[tid]; sWe[tid] = We[tid]; }
    __syncthreads();
    int t = blockIdx.x * blockDim.x + tid;
    if (t >= n_nodes * HIDC) return;
    int n = t >> 4, c = t & 15;
    const float* h = g_agg1 + n * HIDC;
    float acc = 0.f;
#pragma unroll
    for (int k = 0; k < HIDC; k++)
        acc = fmaf(fmaxf(h[k], 0.f), sWn[k * HIDC + c], acc);
    const float4* a4 = (const float4*)(g_A + n * HIDC);
    float ae = 0.f;
#pragma unroll
    for (int j = 0; j < HIDC / 4; j++) {
        float4 v = a4[j];
        ae = fmaf(v.x, sWe[(4 * j + 0) * HIDC + c], ae);
        ae = fmaf(v.y, sWe[(4 * j + 1) * HIDC + c], ae);
        ae = fmaf(v.z, sWe[(4 * j + 2) * HIDC + c], ae);
        ae = fmaf(v.w, sWe[(4 * j + 3) * HIDC + c], ae);
    }
    float di = g_dinv[n];
    g_emb2[t] = acc;
    g_agg2[t] = ae + di * di * acc;
}

// pool (warp-uniform shfl reduce over 32 sorted nodes) + fused final linear
__global__ void k_pool(const void* __restrict__ batch,
                       const float* __restrict__ W,
                       const float* __restrict__ b,
                       float* __restrict__ out,
                       int n_nodes, int nblocks) {
    int tid = threadIdx.x;
    int n = blockIdx.x * blockDim.x + tid;
    int g = -1;
    if (n < n_nodes)
        g = g_w64 ? (int)((const long long*)batch)[n] : ((const int*)batch)[n];
    const unsigned full = 0xffffffffu;
    int g0 = __shfl_sync(full, g, 0);
    bool uni = __all_sync(full, g == g0);
    if (uni && g0 >= 0) {
        float ch[HIDC];
#pragma unroll
        for (int c = 0; c < HIDC; c++) {
            float v = fmaxf(g_agg2[n * HIDC + c], 0.f);
#pragma unroll
            for (int off = 16; off >= 1; off >>= 1)
                v += __shfl_down_sync(full, v, off);
            ch[c] = v;
        }
        if ((tid & 31) == 0) {
            red_add_v4(&g_pool[g0 * HIDC + 0],  make_float4(ch[0],  ch[1],  ch[2],  ch[3]));
            red_add_v4(&g_pool[g0 * HIDC + 4],  make_float4(ch[4],  ch[5],  ch[6],  ch[7]));
            red_add_v4(&g_pool[g0 * HIDC + 8],  make_float4(ch[8],  ch[9],  ch[10], ch[11]));
            red_add_v4(&g_pool[g0 * HIDC + 12], make_float4(ch[12], ch[13], ch[14], ch[15]));
            atomicAdd(&g_cnt[g0], 32);
        }
    } else if (n < n_nodes) {
        atomicAdd(&g_cnt[g], 1);
#pragma unroll
        for (int c = 0; c < HIDC; c++)
            atomicAdd(&g_pool[g * HIDC + c], fmaxf(g_agg2[n * HIDC + c], 0.f));
    }
    // last block computes the final linear
    __shared__ int lastblk;
    __threadfence();
    __syncthreads();
    if (tid == 0) lastblk = (atomicAdd(&g_done, 1) == nblocks - 1);
    __syncthreads();
    if (lastblk) {
        __threadfence();
        for (int t = tid; t < GG * OUTC; t += blockDim.x) {
            int gg = t / OUTC, o = t % OUTC;
            float inv = 1.f / fmaxf((float)g_cnt[gg], 1.f);
            float s = b[o];
#pragma unroll
            for (int k = 0; k < HIDC; k++)
                s = fmaf(g_pool[gg * HIDC + k] * inv, W[k * OUTC + o], s);
            out[t] = s;
        }
    }
}

// ---------------- launch ----------------
extern "C" void kernel_launch(void* const* d_in, const int* in_sizes, int n_in,
                              void* d_out, int out_size) {
    const float* x    = (const float*)d_in[0];
    const void*  ei   = d_in[1];
    const float* ea   = (const float*)d_in[2];
    const void*  bidx = d_in[3];
    const float* W1n  = (const float*)d_in[4];
    const float* W1e  = (const float*)d_in[5];
    const float* W2n  = (const float*)d_in[6];
    const float* W2e  = (const float*)d_in[7];
    const float* nW   = (const float*)d_in[8];
    const float* nb   = (const float*)d_in[9];
    float* out = (float*)d_out;

    int N = in_sizes[0] / INC;
    int E = in_sizes[2] / EDGC;
    if (N > NN) N = NN;
    if (E > EE) E = EE;
    int nb_scan = (N + 1023) / 1024;

    const int B = 256;
    int gridW = (N + (B / 32) - 1) / (B / 32);
    int gridP = (N + B - 1) / B;

    k_pre  <<<(N + B - 1) / B, B>>>((const unsigned*)ei, N);          // 0
    k_deg  <<<(E + B - 1) / B, B>>>(ei, E);                           // 1
    k_scanA<<<nb_scan, 1024>>>(N, nb_scan);                           // 2
    k_fuse <<<(4 * E + B - 1) / B, B>>>((const float4*)ea, E);        // 3 <- profiled
    k_emb1 <<<(N * HIDC + B - 1) / B, B>>>(x, W1n, W1e, N);           // 4
    k_edge <<<gridW, B>>>(1, N);                                      // 5
    k_emb2 <<<(N * HIDC + B - 1) / B, B>>>(W2n, W2e, N);              // 6
    k_edge <<<gridW, B>>>(2, N);                                      // 7
    k_pool <<<gridP, B>>>(bidx, nW, nb, out, N, gridP);               // 8
}